// round 1
// baseline (speedup 1.0000x reference)
#include <cuda_runtime.h>
#include <math.h>

// Problem dims
#define BDIM 32
#define TDIM 64
#define VDIM 50257
#define EDIM 256
#define HDIM 512
#define G4H  2048   // 4*H
#define MROWS 2048  // T*B
#define H2   1024   // 2*H

// Scratch (device globals — no allocations allowed)
__device__ float g_xseq  [MROWS * EDIM];   //  2 MB
__device__ float g_xgates[MROWS * G4H];    // 16 MB
__device__ float g_hgates[BDIM  * G4H];    // 256 KB
__device__ float g_hs    [MROWS * HDIM];   //  4 MB
__device__ float g_hid   [MROWS * H2];     //  8 MB

// ---------------------------------------------------------------------------
// Gather x_seq[m=t*32+b, :] = emb[captions[b, t==0?0:t-1], :]
// ---------------------------------------------------------------------------
__global__ void gather_kernel(const float* __restrict__ emb,
                              const int*   __restrict__ cap,
                              float*       __restrict__ xs)
{
    int m = blockIdx.x;            // 0..2047
    int t = m >> 5, b = m & 31;
    int tt = t ? (t - 1) : 0;
    int tok = cap[b * TDIM + tt];
    const float4* src = (const float4*)(emb + (size_t)tok * EDIM);
    float4*       dst = (float4*)(xs + (size_t)m * EDIM);
    dst[threadIdx.x] = src[threadIdx.x];   // 64 threads x float4 = 256 floats
}

// ---------------------------------------------------------------------------
// h_gates[b,g] = features[b,:] . W_hh[g,:] + b_ih[g] + b_hh[g]
// (both biases folded here; x_gates then needs no bias)
// ---------------------------------------------------------------------------
__global__ void hgates_kernel(const float* __restrict__ feat,
                              const float* __restrict__ Whh,
                              const float* __restrict__ bih,
                              const float* __restrict__ bhh,
                              float*       __restrict__ hg)
{
    int g = blockIdx.x * 8 + (threadIdx.x >> 5);
    int b = threadIdx.x & 31;
    const float4* w = (const float4*)(Whh + (size_t)g * HDIM);
    const float4* f = (const float4*)(feat + (size_t)b * HDIM);
    float s = 0.f;
#pragma unroll 8
    for (int k = 0; k < HDIM / 4; ++k) {
        float4 wv = w[k], fv = f[k];
        s += wv.x * fv.x + wv.y * fv.y + wv.z * fv.z + wv.w * fv.w;
    }
    hg[b * G4H + g] = s + bih[g] + bhh[g];
}

// ---------------------------------------------------------------------------
// LSTM scan. Gates don't depend on h_{t-1} (reference reuses one h_gates),
// so every (b,h) pair is an independent length-64 scalar recurrence.
// ---------------------------------------------------------------------------
__global__ void lstm_kernel(const float* __restrict__ xg,
                            const float* __restrict__ hg,
                            float*       __restrict__ hs)
{
    int idx = blockIdx.x * blockDim.x + threadIdx.x;   // 0..16383
    int b = idx >> 9;          // /512
    int h = idx & 511;
    const float* hgb = hg + (size_t)b * G4H;
    float hi = hgb[h];
    float hf = hgb[512 + h];
    float hgv = hgb[1024 + h];
    float ho = hgb[1536 + h];
    float c = 0.f;
#pragma unroll 4
    for (int t = 0; t < TDIM; ++t) {
        const float* xr = xg + (size_t)(t * BDIM + b) * G4H;
        float gi = xr[h]        + hi;
        float gf = xr[512 + h]  + hf;
        float gg = xr[1024 + h] + hgv;
        float go = xr[1536 + h] + ho;
        float si = 1.f / (1.f + expf(-gi));
        float sf = 1.f / (1.f + expf(-gf));
        float so = 1.f / (1.f + expf(-go));
        c = sf * c + si * tanhf(gg);
        hs[(size_t)(t * BDIM + b) * HDIM + h] = so * tanhf(c);
    }
}

// ---------------------------------------------------------------------------
// SGEMM (NT): C[m,n] = A[m,:K] . B[n,:K] + bias[n]
// BM=BN=128, BK=16, 256 threads, 8x8 register tile (split 4+4 at stride 64
// for conflict-free LDS.128), double-buffered smem.
// PERM=true stores C[( (m&31)*TDIM + (m>>5) )*N + n]  (the b,t,v output layout)
// M is always a multiple of 128 here; N may be ragged (bounds-checked).
// ---------------------------------------------------------------------------
template <bool PERM>
__global__ void __launch_bounds__(256, 2)
sgemm_nt(const float* __restrict__ A, const float* __restrict__ Bm,
         const float* __restrict__ bias, float* __restrict__ C,
         int N, int K)
{
    __shared__ float As[2][16][128];
    __shared__ float Bs[2][16][128];

    const int tid  = threadIdx.x;
    const int bm   = blockIdx.y * 128;
    const int bn   = blockIdx.x * 128;
    const int trow = tid >> 4;          // 0..15
    const int tcol = tid & 15;          // 0..15

    // global->smem staging: thread loads rows r0 and r0+64, float4 at kq0
    const int r0  = tid >> 2;           // 0..63
    const int kq0 = (tid & 3) * 4;      // 0,4,8,12

    const float* Arow0 = A + (size_t)(bm + r0) * K + kq0;
    const float* Arow1 = A + (size_t)(bm + r0 + 64) * K + kq0;
    const int    n0 = bn + r0, n1 = bn + r0 + 64;
    const float* Brow0 = Bm + (size_t)n0 * K + kq0;
    const float* Brow1 = Bm + (size_t)n1 * K + kq0;
    const bool   v0 = (n0 < N), v1 = (n1 < N);

    float acc[8][8];
#pragma unroll
    for (int i = 0; i < 8; ++i)
#pragma unroll
        for (int j = 0; j < 8; ++j) acc[i][j] = 0.f;

    const float4 zero4 = make_float4(0.f, 0.f, 0.f, 0.f);

    // preload tile 0
    float4 a0 = *(const float4*)(Arow0);
    float4 a1 = *(const float4*)(Arow1);
    float4 b0 = v0 ? *(const float4*)(Brow0) : zero4;
    float4 b1 = v1 ? *(const float4*)(Brow1) : zero4;

    As[0][kq0 + 0][r0] = a0.x; As[0][kq0 + 1][r0] = a0.y;
    As[0][kq0 + 2][r0] = a0.z; As[0][kq0 + 3][r0] = a0.w;
    As[0][kq0 + 0][r0 + 64] = a1.x; As[0][kq0 + 1][r0 + 64] = a1.y;
    As[0][kq0 + 2][r0 + 64] = a1.z; As[0][kq0 + 3][r0 + 64] = a1.w;
    Bs[0][kq0 + 0][r0] = b0.x; Bs[0][kq0 + 1][r0] = b0.y;
    Bs[0][kq0 + 2][r0] = b0.z; Bs[0][kq0 + 3][r0] = b0.w;
    Bs[0][kq0 + 0][r0 + 64] = b1.x; Bs[0][kq0 + 1][r0 + 64] = b1.y;
    Bs[0][kq0 + 2][r0 + 64] = b1.z; Bs[0][kq0 + 3][r0 + 64] = b1.w;
    __syncthreads();

    const int nk = K >> 4;
    int buf = 0;
    for (int kt = 0; kt < nk; ++kt) {
        const bool more = (kt + 1 < nk);
        if (more) {
            const int ko = (kt + 1) * 16;
            a0 = *(const float4*)(Arow0 + ko);
            a1 = *(const float4*)(Arow1 + ko);
            b0 = v0 ? *(const float4*)(Brow0 + ko) : zero4;
            b1 = v1 ? *(const float4*)(Brow1 + ko) : zero4;
        }
#pragma unroll
        for (int kk = 0; kk < 16; ++kk) {
            float ra[8], rb[8];
            *(float4*)&ra[0] = *(const float4*)&As[buf][kk][trow * 4];
            *(float4*)&ra[4] = *(const float4*)&As[buf][kk][64 + trow * 4];
            *(float4*)&rb[0] = *(const float4*)&Bs[buf][kk][tcol * 4];
            *(float4*)&rb[4] = *(const float4*)&Bs[buf][kk][64 + tcol * 4];
#pragma unroll
            for (int i = 0; i < 8; ++i)
#pragma unroll
                for (int j = 0; j < 8; ++j)
                    acc[i][j] += ra[i] * rb[j];
        }
        if (more) {
            const int nb = buf ^ 1;
            As[nb][kq0 + 0][r0] = a0.x; As[nb][kq0 + 1][r0] = a0.y;
            As[nb][kq0 + 2][r0] = a0.z; As[nb][kq0 + 3][r0] = a0.w;
            As[nb][kq0 + 0][r0 + 64] = a1.x; As[nb][kq0 + 1][r0 + 64] = a1.y;
            As[nb][kq0 + 2][r0 + 64] = a1.z; As[nb][kq0 + 3][r0 + 64] = a1.w;
            Bs[nb][kq0 + 0][r0] = b0.x; Bs[nb][kq0 + 1][r0] = b0.y;
            Bs[nb][kq0 + 2][r0] = b0.z; Bs[nb][kq0 + 3][r0] = b0.w;
            Bs[nb][kq0 + 0][r0 + 64] = b1.x; Bs[nb][kq0 + 1][r0 + 64] = b1.y;
            Bs[nb][kq0 + 2][r0 + 64] = b1.z; Bs[nb][kq0 + 3][r0 + 64] = b1.w;
            __syncthreads();
            buf = nb;
        }
    }

    // Epilogue
    int cols[8];
    float bv[8];
#pragma unroll
    for (int j = 0; j < 8; ++j) {
        cols[j] = bn + ((j < 4) ? (tcol * 4 + j) : (60 + tcol * 4 + j));
        bv[j] = (bias != nullptr && cols[j] < N) ? bias[cols[j]] : 0.f;
    }
#pragma unroll
    for (int i = 0; i < 8; ++i) {
        int m = bm + ((i < 4) ? (trow * 4 + i) : (60 + trow * 4 + i));
        size_t rowoff;
        if (PERM) {
            int t = m >> 5;      // m = t*32 + b
            int b = m & 31;
            rowoff = (size_t)(b * TDIM + t) * N;
        } else {
            rowoff = (size_t)m * N;
        }
#pragma unroll
        for (int j = 0; j < 8; ++j)
            if (cols[j] < N)
                C[rowoff + cols[j]] = acc[i][j] + bv[j];
    }
}

// ---------------------------------------------------------------------------
extern "C" void kernel_launch(void* const* d_in, const int* in_sizes, int n_in,
                              void* d_out, int out_size)
{
    const float* features = (const float*)d_in[0];
    const int*   captions = (const int*)  d_in[1];
    const float* emb      = (const float*)d_in[2];
    const float* W_ih     = (const float*)d_in[3];
    const float* W_hh     = (const float*)d_in[4];
    const float* b_ih     = (const float*)d_in[5];
    const float* b_hh     = (const float*)d_in[6];
    const float* W1       = (const float*)d_in[7];
    const float* b1       = (const float*)d_in[8];
    const float* W2       = (const float*)d_in[9];
    const float* b2       = (const float*)d_in[10];
    float* out = (float*)d_out;

    float *xseq, *xg, *hg, *hs, *hid;
    cudaGetSymbolAddress((void**)&xseq, g_xseq);
    cudaGetSymbolAddress((void**)&xg,   g_xgates);
    cudaGetSymbolAddress((void**)&hg,   g_hgates);
    cudaGetSymbolAddress((void**)&hs,   g_hs);
    cudaGetSymbolAddress((void**)&hid,  g_hid);

    // 1. gather embedded input sequence (shift-by-one with t=0 -> caption 0)
    gather_kernel<<<MROWS, 64>>>(emb, captions, xseq);

    // 2. h_gates = features @ W_hh^T + b_ih + b_hh   (tiny)
    hgates_kernel<<<G4H / 8, 256>>>(features, W_hh, b_ih, b_hh, hg);

    // 3. x_gates = xseq @ W_ih^T (bias already folded into h_gates)
    {
        dim3 grid(G4H / 128, MROWS / 128);
        sgemm_nt<false><<<grid, 256>>>(xseq, W_ih, nullptr, xg, G4H, EDIM);
    }

    // 4. LSTM scan (independent per (b,h))
    lstm_kernel<<<(BDIM * HDIM) / 256, 256>>>(xg, hg, hs);

    // 5. hid = hs @ W1^T + b1
    {
        dim3 grid(H2 / 128, MROWS / 128);
        sgemm_nt<false><<<grid, 256>>>(hs, W1, b1, hid, H2, HDIM);
    }

    // 6. logits[b,t,v] = hid[(t,b),:] @ W2^T + b2   (dominant GEMM, permuted store)
    {
        dim3 grid((VDIM + 127) / 128, MROWS / 128);
        sgemm_nt<true><<<grid, 256>>>(hid, W2, b2, out, VDIM, H2);
    }
}

// round 5
// speedup vs baseline: 3.4764x; 3.4764x over previous
#include <cuda_runtime.h>
#include <cuda_fp16.h>
#include <math.h>
#include <stdint.h>

// Problem dims
#define BDIM 32
#define TDIM 64
#define VDIM 50257
#define EDIM 256
#define HDIM 512
#define G4H  2048   // 4*H
#define MROWS 2048  // T*B
#define H2   1024   // 2*H

// Scratch (device globals — no allocations allowed)
__device__ float g_xseq  [MROWS * EDIM];
__device__ float g_xgates[MROWS * G4H];
__device__ float g_hgates[BDIM  * G4H];
__device__ float g_hs    [MROWS * HDIM];
__device__ float g_hid   [MROWS * H2];
__device__ __half g_hid_hi[MROWS * H2];
__device__ __half g_hid_lo[MROWS * H2];
__device__ __half g_w2h[(size_t)VDIM * H2];   // ~103 MB (bss)

// ===========================================================================
// helpers
// ===========================================================================
__device__ __forceinline__ uint32_t smem_u32(const void* p) {
    uint32_t a;
    asm("{ .reg .u64 t; cvta.to.shared.u64 t, %1; cvt.u32.u64 %0, t; }"
        : "=r"(a) : "l"(p));
    return a;
}
__device__ __forceinline__ void cp16(uint32_t dst, const void* src, bool ok) {
    int sz = ok ? 16 : 0;
    asm volatile("cp.async.cg.shared.global [%0], [%1], 16, %2;"
                 :: "r"(dst), "l"(src), "r"(sz));
}
__device__ __forceinline__ void ldsm4(uint32_t* r, uint32_t addr) {
    asm volatile("ldmatrix.sync.aligned.m8n8.x4.shared.b16 {%0,%1,%2,%3}, [%4];"
                 : "=r"(r[0]), "=r"(r[1]), "=r"(r[2]), "=r"(r[3]) : "r"(addr));
}
__device__ __forceinline__ void mma16816(float* d, const uint32_t* a, const uint32_t* b) {
    asm volatile("mma.sync.aligned.m16n8k16.row.col.f32.f16.f16.f32 "
                 "{%0,%1,%2,%3}, {%4,%5,%6,%7}, {%8,%9}, {%0,%1,%2,%3};"
                 : "+f"(d[0]), "+f"(d[1]), "+f"(d[2]), "+f"(d[3])
                 : "r"(a[0]), "r"(a[1]), "r"(a[2]), "r"(a[3]),
                   "r"(b[0]), "r"(b[1]));
}

// ===========================================================================
// Small kernels (unchanged)
// ===========================================================================
__global__ void gather_kernel(const float* __restrict__ emb,
                              const int*   __restrict__ cap,
                              float*       __restrict__ xs)
{
    int m = blockIdx.x;
    int t = m >> 5, b = m & 31;
    int tt = t ? (t - 1) : 0;
    int tok = cap[b * TDIM + tt];
    const float4* src = (const float4*)(emb + (size_t)tok * EDIM);
    float4*       dst = (float4*)(xs + (size_t)m * EDIM);
    dst[threadIdx.x] = src[threadIdx.x];
}

__global__ void hgates_kernel(const float* __restrict__ feat,
                              const float* __restrict__ Whh,
                              const float* __restrict__ bih,
                              const float* __restrict__ bhh,
                              float*       __restrict__ hg)
{
    int g = blockIdx.x * 8 + (threadIdx.x >> 5);
    int b = threadIdx.x & 31;
    const float4* w = (const float4*)(Whh + (size_t)g * HDIM);
    const float4* f = (const float4*)(feat + (size_t)b * HDIM);
    float s = 0.f;
#pragma unroll 8
    for (int k = 0; k < HDIM / 4; ++k) {
        float4 wv = w[k], fv = f[k];
        s += wv.x * fv.x + wv.y * fv.y + wv.z * fv.z + wv.w * fv.w;
    }
    hg[b * G4H + g] = s + bih[g] + bhh[g];
}

__global__ void lstm_kernel(const float* __restrict__ xg,
                            const float* __restrict__ hg,
                            float*       __restrict__ hs)
{
    int idx = blockIdx.x * blockDim.x + threadIdx.x;
    int b = idx >> 9;
    int h = idx & 511;
    const float* hgb = hg + (size_t)b * G4H;
    float hi = hgb[h];
    float hf = hgb[512 + h];
    float hgv = hgb[1024 + h];
    float ho = hgb[1536 + h];
    float c = 0.f;
#pragma unroll 4
    for (int t = 0; t < TDIM; ++t) {
        const float* xr = xg + (size_t)(t * BDIM + b) * G4H;
        float gi = xr[h]        + hi;
        float gf = xr[512 + h]  + hf;
        float gg = xr[1024 + h] + hgv;
        float go = xr[1536 + h] + ho;
        float si = 1.f / (1.f + expf(-gi));
        float sf = 1.f / (1.f + expf(-gf));
        float so = 1.f / (1.f + expf(-go));
        c = sf * c + si * tanhf(gg);
        hs[(size_t)(t * BDIM + b) * HDIM + h] = so * tanhf(c);
    }
}

// fp32 -> fp16 (hi only), 4 elems/thread
__global__ void tohalf_kernel(const float* __restrict__ x,
                              __half* __restrict__ h, int n4)
{
    int i = blockIdx.x * blockDim.x + threadIdx.x;
    if (i >= n4) return;
    float4 v = ((const float4*)x)[i];
    __half2* H = (__half2*)h;
    H[2 * i]     = __floats2half2_rn(v.x, v.y);
    H[2 * i + 1] = __floats2half2_rn(v.z, v.w);
}

// fp32 -> fp16 hi + lo residual, 4 elems/thread
__global__ void split_kernel(const float* __restrict__ x,
                             __half* __restrict__ hi,
                             __half* __restrict__ lo, int n4)
{
    int i = blockIdx.x * blockDim.x + threadIdx.x;
    if (i >= n4) return;
    float4 v = ((const float4*)x)[i];
    __half h0 = __float2half_rn(v.x), h1 = __float2half_rn(v.y);
    __half h2 = __float2half_rn(v.z), h3 = __float2half_rn(v.w);
    __half l0 = __float2half_rn(v.x - __half2float(h0));
    __half l1 = __float2half_rn(v.y - __half2float(h1));
    __half l2 = __float2half_rn(v.z - __half2float(h2));
    __half l3 = __float2half_rn(v.w - __half2float(h3));
    __half2* H = (__half2*)hi;
    __half2* L = (__half2*)lo;
    H[2 * i]     = __halves2half2(h0, h1);
    H[2 * i + 1] = __halves2half2(h2, h3);
    L[2 * i]     = __halves2half2(l0, l1);
    L[2 * i + 1] = __halves2half2(l2, l3);
}

// ===========================================================================
// fp32 SGEMM (NT) for the small GEMMs (unchanged from round 1)
// ===========================================================================
template <bool PERM>
__global__ void __launch_bounds__(256, 2)
sgemm_nt(const float* __restrict__ A, const float* __restrict__ Bm,
         const float* __restrict__ bias, float* __restrict__ C,
         int N, int K)
{
    __shared__ float As[2][16][128];
    __shared__ float Bs[2][16][128];

    const int tid  = threadIdx.x;
    const int bm   = blockIdx.y * 128;
    const int bn   = blockIdx.x * 128;
    const int trow = tid >> 4;
    const int tcol = tid & 15;
    const int r0  = tid >> 2;
    const int kq0 = (tid & 3) * 4;

    const float* Arow0 = A + (size_t)(bm + r0) * K + kq0;
    const float* Arow1 = A + (size_t)(bm + r0 + 64) * K + kq0;
    const int    n0 = bn + r0, n1 = bn + r0 + 64;
    const float* Brow0 = Bm + (size_t)n0 * K + kq0;
    const float* Brow1 = Bm + (size_t)n1 * K + kq0;
    const bool   v0 = (n0 < N), v1 = (n1 < N);

    float acc[8][8];
#pragma unroll
    for (int i = 0; i < 8; ++i)
#pragma unroll
        for (int j = 0; j < 8; ++j) acc[i][j] = 0.f;

    const float4 zero4 = make_float4(0.f, 0.f, 0.f, 0.f);

    float4 a0 = *(const float4*)(Arow0);
    float4 a1 = *(const float4*)(Arow1);
    float4 b0 = v0 ? *(const float4*)(Brow0) : zero4;
    float4 b1 = v1 ? *(const float4*)(Brow1) : zero4;

    As[0][kq0 + 0][r0] = a0.x; As[0][kq0 + 1][r0] = a0.y;
    As[0][kq0 + 2][r0] = a0.z; As[0][kq0 + 3][r0] = a0.w;
    As[0][kq0 + 0][r0 + 64] = a1.x; As[0][kq0 + 1][r0 + 64] = a1.y;
    As[0][kq0 + 2][r0 + 64] = a1.z; As[0][kq0 + 3][r0 + 64] = a1.w;
    Bs[0][kq0 + 0][r0] = b0.x; Bs[0][kq0 + 1][r0] = b0.y;
    Bs[0][kq0 + 2][r0] = b0.z; Bs[0][kq0 + 3][r0] = b0.w;
    Bs[0][kq0 + 0][r0 + 64] = b1.x; Bs[0][kq0 + 1][r0 + 64] = b1.y;
    Bs[0][kq0 + 2][r0 + 64] = b1.z; Bs[0][kq0 + 3][r0 + 64] = b1.w;
    __syncthreads();

    const int nk = K >> 4;
    int buf = 0;
    for (int kt = 0; kt < nk; ++kt) {
        const bool more = (kt + 1 < nk);
        if (more) {
            const int ko = (kt + 1) * 16;
            a0 = *(const float4*)(Arow0 + ko);
            a1 = *(const float4*)(Arow1 + ko);
            b0 = v0 ? *(const float4*)(Brow0 + ko) : zero4;
            b1 = v1 ? *(const float4*)(Brow1 + ko) : zero4;
        }
#pragma unroll
        for (int kk = 0; kk < 16; ++kk) {
            float ra[8], rb[8];
            *(float4*)&ra[0] = *(const float4*)&As[buf][kk][trow * 4];
            *(float4*)&ra[4] = *(const float4*)&As[buf][kk][64 + trow * 4];
            *(float4*)&rb[0] = *(const float4*)&Bs[buf][kk][tcol * 4];
            *(float4*)&rb[4] = *(const float4*)&Bs[buf][kk][64 + tcol * 4];
#pragma unroll
            for (int i = 0; i < 8; ++i)
#pragma unroll
                for (int j = 0; j < 8; ++j)
                    acc[i][j] += ra[i] * rb[j];
        }
        if (more) {
            const int nb = buf ^ 1;
            As[nb][kq0 + 0][r0] = a0.x; As[nb][kq0 + 1][r0] = a0.y;
            As[nb][kq0 + 2][r0] = a0.z; As[nb][kq0 + 3][r0] = a0.w;
            As[nb][kq0 + 0][r0 + 64] = a1.x; As[nb][kq0 + 1][r0 + 64] = a1.y;
            As[nb][kq0 + 2][r0 + 64] = a1.z; As[nb][kq0 + 3][r0 + 64] = a1.w;
            Bs[nb][kq0 + 0][r0] = b0.x; Bs[nb][kq0 + 1][r0] = b0.y;
            Bs[nb][kq0 + 2][r0] = b0.z; Bs[nb][kq0 + 3][r0] = b0.w;
            Bs[nb][kq0 + 0][r0 + 64] = b1.x; Bs[nb][kq0 + 1][r0 + 64] = b1.y;
            Bs[nb][kq0 + 2][r0 + 64] = b1.z; Bs[nb][kq0 + 3][r0 + 64] = b1.w;
            __syncthreads();
            buf = nb;
        }
    }

    int cols[8];
    float bv[8];
#pragma unroll
    for (int j = 0; j < 8; ++j) {
        cols[j] = bn + ((j < 4) ? (tcol * 4 + j) : (60 + tcol * 4 + j));
        bv[j] = (bias != nullptr && cols[j] < N) ? bias[cols[j]] : 0.f;
    }
#pragma unroll
    for (int i = 0; i < 8; ++i) {
        int m = bm + ((i < 4) ? (trow * 4 + i) : (60 + trow * 4 + i));
        size_t rowoff;
        if (PERM) {
            int t = m >> 5;
            int b = m & 31;
            rowoff = (size_t)(b * TDIM + t) * N;
        } else {
            rowoff = (size_t)m * N;
        }
#pragma unroll
        for (int j = 0; j < 8; ++j)
            if (cols[j] < N)
                C[rowoff + cols[j]] = acc[i][j] + bv[j];
    }
}

// ===========================================================================
// GEMM5 via mma.sync fp16 (HMMA), split-A 2-product:
//   C = (Ahi + Alo) @ B^T + bias, fp32 accum
// BM=128, BN=128, BK=32, 256 threads (4x2 warps of 32x64), 2-stage cp.async.
// Output rows permuted: m = t*32+b  ->  out row b*64+t.
// ===========================================================================
#define G5_BM 128
#define G5_BN 128
#define G5_BK 32
#define G5_NKT (H2 / G5_BK)        // 32
#define ROWB 80                    // padded smem row stride (bytes) -> conflict-free ldsm
#define TILEB (128 * ROWB)         // 10240 per tile
#define STAGEB (3 * TILEB)         // Ahi, Alo, B
#define G5_SMEM (2 * STAGEB)       // 61440

__global__ void __launch_bounds__(256, 2)
gemm5_hmma(const __half* __restrict__ Ahi, const __half* __restrict__ Alo,
           const __half* __restrict__ Bh,
           const float* __restrict__ bias, float* __restrict__ C)
{
    extern __shared__ char sm[];
    const uint32_t sbase = smem_u32(sm);

    const int tid  = threadIdx.x;
    const int wid  = tid >> 5;
    const int lane = tid & 31;
    const int warp_m = wid & 3;       // 0..3 -> m offset 32*warp_m
    const int warp_n = wid >> 2;      // 0..1 -> n offset 64*warp_n
    const int bm = blockIdx.x * G5_BM;
    const int bn = blockIdx.y * G5_BN;

    // ldmatrix per-lane byte offsets (within stage)
    const uint32_t a_off = (uint32_t)((warp_m * 32 + (lane & 15)) * ROWB + (lane >> 4) * 16);
    const uint32_t b_off = (uint32_t)(2 * TILEB +
                     (warp_n * 64 + ((lane >> 4) & 1) * 8 + (lane & 7)) * ROWB +
                     ((lane >> 3) & 1) * 16);

    float acc[2][8][4];
#pragma unroll
    for (int mt = 0; mt < 2; ++mt)
#pragma unroll
        for (int nt = 0; nt < 8; ++nt)
#pragma unroll
            for (int e = 0; e < 4; ++e) acc[mt][nt][e] = 0.f;

    // ------- stage loader: 1536 x 16B chunks, 6 per thread -------
    auto load_stage = [&](int kt) {
        const uint32_t sb = sbase + (uint32_t)(kt & 1) * STAGEB;
        const int k0 = kt * G5_BK;
#pragma unroll
        for (int i = 0; i < 6; ++i) {
            int c  = tid + (i << 8);
            int t3 = c >> 9;            // 0 = Ahi, 1 = Alo, 2 = B
            int w  = c & 511;
            int r  = w >> 2;
            int ch = w & 3;
            uint32_t dst = sb + (uint32_t)(t3 * TILEB + r * ROWB + ch * 16);
            if (t3 == 0) {
                cp16(dst, Ahi + (size_t)(bm + r) * H2 + k0 + ch * 8, true);
            } else if (t3 == 1) {
                cp16(dst, Alo + (size_t)(bm + r) * H2 + k0 + ch * 8, true);
            } else {
                int gr = bn + r;
                bool ok = gr < VDIM;
                cp16(dst, Bh + (size_t)(ok ? gr : 0) * H2 + k0 + ch * 8, ok);
            }
        }
    };

    load_stage(0);
    asm volatile("cp.async.commit_group;" ::: "memory");
    load_stage(1);
    asm volatile("cp.async.commit_group;" ::: "memory");

    for (int kt = 0; kt < G5_NKT; ++kt) {
        asm volatile("cp.async.wait_group 1;" ::: "memory");
        __syncthreads();

        const uint32_t sb = sbase + (uint32_t)(kt & 1) * STAGEB;
#pragma unroll
        for (int s = 0; s < 2; ++s) {
            uint32_t Ah[2][4], Al[2][4], Bf[4][4];
#pragma unroll
            for (int mt = 0; mt < 2; ++mt) {
                ldsm4(Ah[mt], sb + a_off + (uint32_t)(mt * 16 * ROWB + s * 32));
                ldsm4(Al[mt], sb + TILEB + a_off + (uint32_t)(mt * 16 * ROWB + s * 32));
            }
#pragma unroll
            for (int q = 0; q < 4; ++q)
                ldsm4(Bf[q], sb + b_off + (uint32_t)(q * 16 * ROWB + s * 32));
#pragma unroll
            for (int mt = 0; mt < 2; ++mt)
#pragma unroll
                for (int nt = 0; nt < 8; ++nt) {
                    const uint32_t* bp = &Bf[nt >> 1][(nt & 1) * 2];
                    mma16816(acc[mt][nt], Ah[mt], bp);
                    mma16816(acc[mt][nt], Al[mt], bp);
                }
        }
        __syncthreads();
        if (kt + 2 < G5_NKT) load_stage(kt + 2);
        asm volatile("cp.async.commit_group;" ::: "memory");
    }

    // ------- epilogue: bias + permuted store -------
    const int c0 = bn + warp_n * 64 + (lane & 3) * 2;
    float bv[8][2];
#pragma unroll
    for (int nt = 0; nt < 8; ++nt) {
        int n = c0 + nt * 8;
        bv[nt][0] = (n     < VDIM) ? bias[n]     : 0.f;
        bv[nt][1] = (n + 1 < VDIM) ? bias[n + 1] : 0.f;
    }
    const int r0 = bm + warp_m * 32 + (lane >> 2);
#pragma unroll
    for (int mt = 0; mt < 2; ++mt) {
#pragma unroll
        for (int h = 0; h < 2; ++h) {
            int m = r0 + mt * 16 + h * 8;
            int t = m >> 5, b = m & 31;
            size_t orow = (size_t)(b * TDIM + t) * VDIM;
#pragma unroll
            for (int nt = 0; nt < 8; ++nt) {
                int n = c0 + nt * 8;
                if (n < VDIM)     C[orow + n]     = acc[mt][nt][h * 2 + 0] + bv[nt][0];
                if (n + 1 < VDIM) C[orow + n + 1] = acc[mt][nt][h * 2 + 1] + bv[nt][1];
            }
        }
    }
}

// ===========================================================================
extern "C" void kernel_launch(void* const* d_in, const int* in_sizes, int n_in,
                              void* d_out, int out_size)
{
    const float* features = (const float*)d_in[0];
    const int*   captions = (const int*)  d_in[1];
    const float* emb      = (const float*)d_in[2];
    const float* W_ih     = (const float*)d_in[3];
    const float* W_hh     = (const float*)d_in[4];
    const float* b_ih     = (const float*)d_in[5];
    const float* b_hh     = (const float*)d_in[6];
    const float* W1       = (const float*)d_in[7];
    const float* b1       = (const float*)d_in[8];
    const float* W2       = (const float*)d_in[9];
    const float* b2       = (const float*)d_in[10];
    float* out = (float*)d_out;

    float *xseq, *xg, *hg, *hs, *hid;
    __half *hid_hi, *hid_lo, *w2h;
    cudaGetSymbolAddress((void**)&xseq,   g_xseq);
    cudaGetSymbolAddress((void**)&xg,     g_xgates);
    cudaGetSymbolAddress((void**)&hg,     g_hgates);
    cudaGetSymbolAddress((void**)&hs,     g_hs);
    cudaGetSymbolAddress((void**)&hid,    g_hid);
    cudaGetSymbolAddress((void**)&hid_hi, g_hid_hi);
    cudaGetSymbolAddress((void**)&hid_lo, g_hid_lo);
    cudaGetSymbolAddress((void**)&w2h,    g_w2h);

    cudaFuncSetAttribute(gemm5_hmma,
                         cudaFuncAttributeMaxDynamicSharedMemorySize, G5_SMEM);

    // W2 -> fp16 (big, independent — launch first)
    {
        int n4 = (VDIM * H2) / 4;
        tohalf_kernel<<<(n4 + 255) / 256, 256>>>(W2, w2h, n4);
    }

    // 1. gather embedded input sequence
    gather_kernel<<<MROWS, 64>>>(emb, captions, xseq);

    // 2. h_gates = features @ W_hh^T + b_ih + b_hh
    hgates_kernel<<<G4H / 8, 256>>>(features, W_hh, b_ih, b_hh, hg);

    // 3. x_gates = xseq @ W_ih^T
    {
        dim3 grid(G4H / 128, MROWS / 128);
        sgemm_nt<false><<<grid, 256>>>(xseq, W_ih, nullptr, xg, G4H, EDIM);
    }

    // 4. LSTM scan
    lstm_kernel<<<(BDIM * HDIM) / 256, 256>>>(xg, hg, hs);

    // 5. hid = hs @ W1^T + b1
    {
        dim3 grid(H2 / 128, MROWS / 128);
        sgemm_nt<false><<<grid, 256>>>(hs, W1, b1, hid, H2, HDIM);
    }

    // 5b. hid -> fp16 hi/lo
    {
        int n4 = (MROWS * H2) / 4;
        split_kernel<<<(n4 + 255) / 256, 256>>>(hid, hid_hi, hid_lo, n4);
    }

    // 6. logits = hid @ W2^T + b2  (HMMA, split-A, permuted store)
    {
        dim3 grid(MROWS / G5_BM, (VDIM + G5_BN - 1) / G5_BN);  // m-fast: B tiles L2-resident
        gemm5_hmma<<<grid, 256, G5_SMEM>>>(hid_hi, hid_lo, w2h, b2, out);
    }
}

// round 14
// speedup vs baseline: 4.9936x; 1.4364x over previous
#include <cuda_runtime.h>
#include <cuda_fp16.h>
#include <math.h>
#include <stdint.h>

// Problem dims
#define BDIM 32
#define TDIM 64
#define VDIM 50257
#define EDIM 256
#define HDIM 512
#define G4H  2048   // 4*H
#define MROWS 2048  // T*B
#define H2   1024   // 2*H

// Scratch (device globals — no allocations allowed)
__device__ float g_xseq  [MROWS * EDIM];
__device__ float g_xgates[MROWS * G4H];
__device__ float g_hgates[BDIM  * G4H];
__device__ float g_hs    [MROWS * HDIM];
__device__ float g_hid   [MROWS * H2];
__device__ __half g_hidh[MROWS * H2];
__device__ __half g_w2h[(size_t)VDIM * H2];   // ~103 MB (bss)

// ===========================================================================
// helpers
// ===========================================================================
__device__ __forceinline__ uint32_t smem_u32(const void* p) {
    uint32_t a;
    asm("{ .reg .u64 t; cvta.to.shared.u64 t, %1; cvt.u32.u64 %0, t; }"
        : "=r"(a) : "l"(p));
    return a;
}
__device__ __forceinline__ void cp16(uint32_t dst, const void* src, bool ok) {
    int sz = ok ? 16 : 0;
    asm volatile("cp.async.cg.shared.global [%0], [%1], 16, %2;"
                 :: "r"(dst), "l"(src), "r"(sz));
}
__device__ __forceinline__ void ldsm4(uint32_t* r, uint32_t addr) {
    asm volatile("ldmatrix.sync.aligned.m8n8.x4.shared.b16 {%0,%1,%2,%3}, [%4];"
                 : "=r"(r[0]), "=r"(r[1]), "=r"(r[2]), "=r"(r[3]) : "r"(addr));
}
__device__ __forceinline__ void mma16816(float* d, const uint32_t* a, const uint32_t* b) {
    asm volatile("mma.sync.aligned.m16n8k16.row.col.f32.f16.f16.f32 "
                 "{%0,%1,%2,%3}, {%4,%5,%6,%7}, {%8,%9}, {%0,%1,%2,%3};"
                 : "+f"(d[0]), "+f"(d[1]), "+f"(d[2]), "+f"(d[3])
                 : "r"(a[0]), "r"(a[1]), "r"(a[2]), "r"(a[3]),
                   "r"(b[0]), "r"(b[1]));
}

// ===========================================================================
// Small kernels
// ===========================================================================
__global__ void gather_kernel(const float* __restrict__ emb,
                              const int*   __restrict__ cap,
                              float*       __restrict__ xs)
{
    int m = blockIdx.x;
    int t = m >> 5, b = m & 31;
    int tt = t ? (t - 1) : 0;
    int tok = cap[b * TDIM + tt];
    const float4* src = (const float4*)(emb + (size_t)tok * EDIM);
    float4*       dst = (float4*)(xs + (size_t)m * EDIM);
    dst[threadIdx.x] = src[threadIdx.x];
}

__global__ void hgates_kernel(const float* __restrict__ feat,
                              const float* __restrict__ Whh,
                              const float* __restrict__ bih,
                              const float* __restrict__ bhh,
                              float*       __restrict__ hg)
{
    int g = blockIdx.x * 8 + (threadIdx.x >> 5);
    int b = threadIdx.x & 31;
    const float4* w = (const float4*)(Whh + (size_t)g * HDIM);
    const float4* f = (const float4*)(feat + (size_t)b * HDIM);
    float s = 0.f;
#pragma unroll 8
    for (int k = 0; k < HDIM / 4; ++k) {
        float4 wv = w[k], fv = f[k];
        s += wv.x * fv.x + wv.y * fv.y + wv.z * fv.z + wv.w * fv.w;
    }
    hg[b * G4H + g] = s + bih[g] + bhh[g];
}

__global__ void lstm_kernel(const float* __restrict__ xg,
                            const float* __restrict__ hg,
                            float*       __restrict__ hs)
{
    int idx = blockIdx.x * blockDim.x + threadIdx.x;
    int b = idx >> 9;
    int h = idx & 511;
    const float* hgb = hg + (size_t)b * G4H;
    float hi = hgb[h];
    float hf = hgb[512 + h];
    float hgv = hgb[1024 + h];
    float ho = hgb[1536 + h];
    float c = 0.f;
#pragma unroll 4
    for (int t = 0; t < TDIM; ++t) {
        const float* xr = xg + (size_t)(t * BDIM + b) * G4H;
        float gi = xr[h]        + hi;
        float gf = xr[512 + h]  + hf;
        float gg = xr[1024 + h] + hgv;
        float go = xr[1536 + h] + ho;
        float si = 1.f / (1.f + expf(-gi));
        float sf = 1.f / (1.f + expf(-gf));
        float so = 1.f / (1.f + expf(-go));
        c = sf * c + si * tanhf(gg);
        hs[(size_t)(t * BDIM + b) * HDIM + h] = so * tanhf(c);
    }
}

// fp32 -> fp16, 4 elems/thread
__global__ void tohalf_kernel(const float* __restrict__ x,
                              __half* __restrict__ h, int n4)
{
    int i = blockIdx.x * blockDim.x + threadIdx.x;
    if (i >= n4) return;
    float4 v = ((const float4*)x)[i];
    __half2* H = (__half2*)h;
    H[2 * i]     = __floats2half2_rn(v.x, v.y);
    H[2 * i + 1] = __floats2half2_rn(v.z, v.w);
}

// ===========================================================================
// fp32 SGEMM (NT) for the small GEMMs
// ===========================================================================
template <bool PERM>
__global__ void __launch_bounds__(256, 2)
sgemm_nt(const float* __restrict__ A, const float* __restrict__ Bm,
         const float* __restrict__ bias, float* __restrict__ C,
         int N, int K)
{
    __shared__ float As[2][16][128];
    __shared__ float Bs[2][16][128];

    const int tid  = threadIdx.x;
    const int bm   = blockIdx.y * 128;
    const int bn   = blockIdx.x * 128;
    const int trow = tid >> 4;
    const int tcol = tid & 15;
    const int r0  = tid >> 2;
    const int kq0 = (tid & 3) * 4;

    const float* Arow0 = A + (size_t)(bm + r0) * K + kq0;
    const float* Arow1 = A + (size_t)(bm + r0 + 64) * K + kq0;
    const int    n0 = bn + r0, n1 = bn + r0 + 64;
    const float* Brow0 = Bm + (size_t)n0 * K + kq0;
    const float* Brow1 = Bm + (size_t)n1 * K + kq0;
    const bool   v0 = (n0 < N), v1 = (n1 < N);

    float acc[8][8];
#pragma unroll
    for (int i = 0; i < 8; ++i)
#pragma unroll
        for (int j = 0; j < 8; ++j) acc[i][j] = 0.f;

    const float4 zero4 = make_float4(0.f, 0.f, 0.f, 0.f);

    float4 a0 = *(const float4*)(Arow0);
    float4 a1 = *(const float4*)(Arow1);
    float4 b0 = v0 ? *(const float4*)(Brow0) : zero4;
    float4 b1 = v1 ? *(const float4*)(Brow1) : zero4;

    As[0][kq0 + 0][r0] = a0.x; As[0][kq0 + 1][r0] = a0.y;
    As[0][kq0 + 2][r0] = a0.z; As[0][kq0 + 3][r0] = a0.w;
    As[0][kq0 + 0][r0 + 64] = a1.x; As[0][kq0 + 1][r0 + 64] = a1.y;
    As[0][kq0 + 2][r0 + 64] = a1.z; As[0][kq0 + 3][r0 + 64] = a1.w;
    Bs[0][kq0 + 0][r0] = b0.x; Bs[0][kq0 + 1][r0] = b0.y;
    Bs[0][kq0 + 2][r0] = b0.z; Bs[0][kq0 + 3][r0] = b0.w;
    Bs[0][kq0 + 0][r0 + 64] = b1.x; Bs[0][kq0 + 1][r0 + 64] = b1.y;
    Bs[0][kq0 + 2][r0 + 64] = b1.z; Bs[0][kq0 + 3][r0 + 64] = b1.w;
    __syncthreads();

    const int nk = K >> 4;
    int buf = 0;
    for (int kt = 0; kt < nk; ++kt) {
        const bool more = (kt + 1 < nk);
        if (more) {
            const int ko = (kt + 1) * 16;
            a0 = *(const float4*)(Arow0 + ko);
            a1 = *(const float4*)(Arow1 + ko);
            b0 = v0 ? *(const float4*)(Brow0 + ko) : zero4;
            b1 = v1 ? *(const float4*)(Brow1 + ko) : zero4;
        }
#pragma unroll
        for (int kk = 0; kk < 16; ++kk) {
            float ra[8], rb[8];
            *(float4*)&ra[0] = *(const float4*)&As[buf][kk][trow * 4];
            *(float4*)&ra[4] = *(const float4*)&As[buf][kk][64 + trow * 4];
            *(float4*)&rb[0] = *(const float4*)&Bs[buf][kk][tcol * 4];
            *(float4*)&rb[4] = *(const float4*)&Bs[buf][kk][64 + tcol * 4];
#pragma unroll
            for (int i = 0; i < 8; ++i)
#pragma unroll
                for (int j = 0; j < 8; ++j)
                    acc[i][j] += ra[i] * rb[j];
        }
        if (more) {
            const int nb = buf ^ 1;
            As[nb][kq0 + 0][r0] = a0.x; As[nb][kq0 + 1][r0] = a0.y;
            As[nb][kq0 + 2][r0] = a0.z; As[nb][kq0 + 3][r0] = a0.w;
            As[nb][kq0 + 0][r0 + 64] = a1.x; As[nb][kq0 + 1][r0 + 64] = a1.y;
            As[nb][kq0 + 2][r0 + 64] = a1.z; As[nb][kq0 + 3][r0 + 64] = a1.w;
            Bs[nb][kq0 + 0][r0] = b0.x; Bs[nb][kq0 + 1][r0] = b0.y;
            Bs[nb][kq0 + 2][r0] = b0.z; Bs[nb][kq0 + 3][r0] = b0.w;
            Bs[nb][kq0 + 0][r0 + 64] = b1.x; Bs[nb][kq0 + 1][r0 + 64] = b1.y;
            Bs[nb][kq0 + 2][r0 + 64] = b1.z; Bs[nb][kq0 + 3][r0 + 64] = b1.w;
            __syncthreads();
            buf = nb;
        }
    }

    int cols[8];
    float bv[8];
#pragma unroll
    for (int j = 0; j < 8; ++j) {
        cols[j] = bn + ((j < 4) ? (tcol * 4 + j) : (60 + tcol * 4 + j));
        bv[j] = (bias != nullptr && cols[j] < N) ? bias[cols[j]] : 0.f;
    }
#pragma unroll
    for (int i = 0; i < 8; ++i) {
        int m = bm + ((i < 4) ? (trow * 4 + i) : (60 + trow * 4 + i));
        size_t rowoff;
        if (PERM) {
            int t = m >> 5;
            int b = m & 31;
            rowoff = (size_t)(b * TDIM + t) * N;
        } else {
            rowoff = (size_t)m * N;
        }
#pragma unroll
        for (int j = 0; j < 8; ++j)
            if (cols[j] < N)
                C[rowoff + cols[j]] = acc[i][j] + bv[j];
    }
}

// ===========================================================================
// GEMM5 via mma.sync fp16 (HMMA), single product:
//   C = A @ B^T + bias, fp32 accum
// BM=128, BN=128, BK=32, 256 threads (4x2 warps of 32x64),
// 4-stage cp.async pipeline, ONE __syncthreads per k-iter.
// Output rows permuted: m = t*32+b  ->  out row b*64+t.
// NOTE: VDIM=50257 is ODD -> output rows are only 4B-aligned; all stores
// MUST be scalar st.32 (st.64 traps with misaligned address).
// ===========================================================================
#define G5_BM 128
#define G5_BN 128
#define G5_BK 32
#define G5_NKT (H2 / G5_BK)        // 32
#define ROWB 80                    // padded smem row stride (bytes), 5*16B: conflict-free ldsm
#define TILEB (128 * ROWB)         // 10240 per tile
#define STAGEB (2 * TILEB)         // A, B          = 20480
#define G5_STAGES 4
#define G5_SMEM (G5_STAGES * STAGEB)   // 81920

__global__ void __launch_bounds__(256, 2)
gemm5_hmma(const __half* __restrict__ Ah, const __half* __restrict__ Bh,
           const float* __restrict__ bias, float* __restrict__ C)
{
    extern __shared__ char sm[];
    const uint32_t sbase = smem_u32(sm);

    const int tid  = threadIdx.x;
    const int wid  = tid >> 5;
    const int lane = tid & 31;
    const int warp_m = wid & 3;       // m offset 32*warp_m
    const int warp_n = wid >> 2;      // n offset 64*warp_n
    const int bm = blockIdx.x * G5_BM;
    const int bn = blockIdx.y * G5_BN;

    // ldmatrix per-lane byte offsets (within stage)
    const uint32_t a_off = (uint32_t)((warp_m * 32 + (lane & 15)) * ROWB + (lane >> 4) * 16);
    const uint32_t b_off = (uint32_t)(TILEB +
                     (warp_n * 64 + ((lane >> 4) & 1) * 8 + (lane & 7)) * ROWB +
                     ((lane >> 3) & 1) * 16);

    float acc[2][8][4];
#pragma unroll
    for (int mt = 0; mt < 2; ++mt)
#pragma unroll
        for (int nt = 0; nt < 8; ++nt)
#pragma unroll
            for (int e = 0; e < 4; ++e) acc[mt][nt][e] = 0.f;

    // stage loader: 1024 x 16B chunks (A 512 + B 512), 4 per thread
    auto load_stage = [&](int kt) {
        const uint32_t sb = sbase + (uint32_t)(kt & (G5_STAGES - 1)) * STAGEB;
        const int k0 = kt * G5_BK;
#pragma unroll
        for (int i = 0; i < 4; ++i) {
            int c  = tid + (i << 8);        // 0..1023
            int t2 = c >> 9;                // 0 = A, 1 = B
            int w  = c & 511;
            int r  = w >> 2;
            int ch = w & 3;
            uint32_t dst = sb + (uint32_t)(t2 * TILEB + r * ROWB + ch * 16);
            if (t2 == 0) {
                cp16(dst, Ah + (size_t)(bm + r) * H2 + k0 + ch * 8, true);
            } else {
                int gr = bn + r;
                bool ok = gr < VDIM;
                cp16(dst, Bh + (size_t)(ok ? gr : 0) * H2 + k0 + ch * 8, ok);
            }
        }
    };

    // prologue: stages 0..2
    load_stage(0);
    asm volatile("cp.async.commit_group;" ::: "memory");
    load_stage(1);
    asm volatile("cp.async.commit_group;" ::: "memory");
    load_stage(2);
    asm volatile("cp.async.commit_group;" ::: "memory");

    for (int kt = 0; kt < G5_NKT; ++kt) {
        asm volatile("cp.async.wait_group 2;" ::: "memory");   // tile kt arrived
        __syncthreads();   // publishes tile kt; all warps done with tile kt-1's slot

        // refill the slot freed last iter with tile kt+3
        if (kt + 3 < G5_NKT) load_stage(kt + 3);
        asm volatile("cp.async.commit_group;" ::: "memory");

        const uint32_t sb = sbase + (uint32_t)(kt & (G5_STAGES - 1)) * STAGEB;
#pragma unroll
        for (int s = 0; s < 2; ++s) {
            uint32_t Af[2][4], Bf[4][4];
#pragma unroll
            for (int mt = 0; mt < 2; ++mt)
                ldsm4(Af[mt], sb + a_off + (uint32_t)(mt * 16 * ROWB + s * 32));
#pragma unroll
            for (int q = 0; q < 4; ++q)
                ldsm4(Bf[q], sb + b_off + (uint32_t)(q * 16 * ROWB + s * 32));
#pragma unroll
            for (int mt = 0; mt < 2; ++mt)
#pragma unroll
                for (int nt = 0; nt < 8; ++nt)
                    mma16816(acc[mt][nt], Af[mt], &Bf[nt >> 1][(nt & 1) * 2]);
        }
    }

    // ------- epilogue: bias + permuted store (SCALAR st.32 only) -------
    const int c0 = bn + warp_n * 64 + (lane & 3) * 2;
    float bv[8][2];
#pragma unroll
    for (int nt = 0; nt < 8; ++nt) {
        int n = c0 + nt * 8;
        bv[nt][0] = (n     < VDIM) ? bias[n]     : 0.f;
        bv[nt][1] = (n + 1 < VDIM) ? bias[n + 1] : 0.f;
    }
    const int r0 = bm + warp_m * 32 + (lane >> 2);
#pragma unroll
    for (int mt = 0; mt < 2; ++mt) {
#pragma unroll
        for (int h = 0; h < 2; ++h) {
            int m = r0 + mt * 16 + h * 8;
            int t = m >> 5, b = m & 31;
            size_t orow = (size_t)(b * TDIM + t) * VDIM;
#pragma unroll
            for (int nt = 0; nt < 8; ++nt) {
                int n = c0 + nt * 8;
                if (n < VDIM)     C[orow + n]     = acc[mt][nt][h * 2 + 0] + bv[nt][0];
                if (n + 1 < VDIM) C[orow + n + 1] = acc[mt][nt][h * 2 + 1] + bv[nt][1];
            }
        }
    }
}

// ===========================================================================
extern "C" void kernel_launch(void* const* d_in, const int* in_sizes, int n_in,
                              void* d_out, int out_size)
{
    const float* features = (const float*)d_in[0];
    const int*   captions = (const int*)  d_in[1];
    const float* emb      = (const float*)d_in[2];
    const float* W_ih     = (const float*)d_in[3];
    const float* W_hh     = (const float*)d_in[4];
    const float* b_ih     = (const float*)d_in[5];
    const float* b_hh     = (const float*)d_in[6];
    const float* W1       = (const float*)d_in[7];
    const float* b1       = (const float*)d_in[8];
    const float* W2       = (const float*)d_in[9];
    const float* b2       = (const float*)d_in[10];
    float* out = (float*)d_out;

    float *xseq, *xg, *hg, *hs, *hid;
    __half *hidh, *w2h;
    cudaGetSymbolAddress((void**)&xseq, g_xseq);
    cudaGetSymbolAddress((void**)&xg,   g_xgates);
    cudaGetSymbolAddress((void**)&hg,   g_hgates);
    cudaGetSymbolAddress((void**)&hs,   g_hs);
    cudaGetSymbolAddress((void**)&hid,  g_hid);
    cudaGetSymbolAddress((void**)&hidh, g_hidh);
    cudaGetSymbolAddress((void**)&w2h,  g_w2h);

    cudaFuncSetAttribute(gemm5_hmma,
                         cudaFuncAttributeMaxDynamicSharedMemorySize, G5_SMEM);

    // W2 -> fp16
    {
        int n4 = (VDIM * H2) / 4;
        tohalf_kernel<<<(n4 + 255) / 256, 256>>>(W2, w2h, n4);
    }

    // 1. gather embedded input sequence
    gather_kernel<<<MROWS, 64>>>(emb, captions, xseq);

    // 2. h_gates = features @ W_hh^T + b_ih + b_hh
    hgates_kernel<<<G4H / 8, 256>>>(features, W_hh, b_ih, b_hh, hg);

    // 3. x_gates = xseq @ W_ih^T
    {
        dim3 grid(G4H / 128, MROWS / 128);
        sgemm_nt<false><<<grid, 256>>>(xseq, W_ih, nullptr, xg, G4H, EDIM);
    }

    // 4. LSTM scan
    lstm_kernel<<<(BDIM * HDIM) / 256, 256>>>(xg, hg, hs);

    // 5. hid = hs @ W1^T + b1
    {
        dim3 grid(H2 / 128, MROWS / 128);
        sgemm_nt<false><<<grid, 256>>>(hs, W1, b1, hid, H2, HDIM);
    }

    // 5b. hid -> fp16
    {
        int n4 = (MROWS * H2) / 4;
        tohalf_kernel<<<(n4 + 255) / 256, 256>>>(hid, hidh, n4);
    }

    // 6. logits = hid @ W2^T + b2  (HMMA single product, permuted store)
    {
        dim3 grid(MROWS / G5_BM, (VDIM + G5_BN - 1) / G5_BN);  // m-fast: B tiles L2-resident
        gemm5_hmma<<<grid, 256, G5_SMEM>>>(hidh, w2h, b2, out);
    }
}